// round 1
// baseline (speedup 1.0000x reference)
#include <cuda_runtime.h>
#include <math.h>

#define HH 224
#define WW 224
#define BB 2
#define PP 2048
#define FF 256
#define SIGMA_F 0.0003f

// Per-face precomputed screen/camera-space data. 34 floats = 136 B; 256 faces = 34 KB shared.
struct FaceData {
    float x0, y0, x1, y1, x2, y2;          // projected vertices
    float a0, b0, a1, b1, invden;          // barycentric coefficients
    float z0, z1, z2;                      // camera-space z per vertex
    float e01x, e01y, i01;                 // edge v0->v1, 1/(|e|^2+eps)
    float e12x, e12y, i12;                 // edge v1->v2
    float e20x, e20y, i20;                 // edge v2->v0
    float c00, c01, c02;                   // colors vertex 0
    float c10, c11, c12;                   // colors vertex 1
    float c20, c21, c22;                   // colors vertex 2
    float front;                           // 1.0 if normal.z > 0 else 0.0
};

__device__ FaceData g_face[BB][FF];

// ---------------------------------------------------------------------------
// Kernel 1: per-face precompute (B blocks x 256 threads, one thread per face).
// Also writes the normal1 output.
// ---------------------------------------------------------------------------
__global__ void vcr_prep_kernel(const float* __restrict__ pts,
                                const int*   __restrict__ faces,
                                const float* __restrict__ rot,
                                const float* __restrict__ pos,
                                const float* __restrict__ proj,
                                const float* __restrict__ cols,
                                float* __restrict__ out)
{
    int b = blockIdx.x;
    int f = threadIdx.x;
    if (f >= FF) return;

    float R0 = rot[b * 9 + 0], R1 = rot[b * 9 + 1], R2 = rot[b * 9 + 2];
    float R3 = rot[b * 9 + 3], R4 = rot[b * 9 + 4], R5 = rot[b * 9 + 5];
    float R6 = rot[b * 9 + 6], R7 = rot[b * 9 + 7], R8 = rot[b * 9 + 8];
    float cpx = pos[b * 3 + 0], cpy = pos[b * 3 + 1], cpz = pos[b * 3 + 2];
    float pr0 = proj[0], pr1 = proj[1], pr2 = proj[2];

    int vi0 = faces[f * 3 + 0];
    int vi1 = faces[f * 3 + 1];
    int vi2 = faces[f * 3 + 2];
    int vi[3] = {vi0, vi1, vi2};

    float Px[3], Py[3], Pz[3], Qx[3], Qy[3];
    float C[3][3];
    #pragma unroll
    for (int k = 0; k < 3; k++) {
        const float* pp = pts + ((size_t)b * PP + vi[k]) * 3;
        float dx = pp[0] - cpx, dy = pp[1] - cpy, dz = pp[2] - cpz;
        float cx = R0 * dx + R1 * dy + R2 * dz;
        float cy = R3 * dx + R4 * dy + R5 * dz;
        float cz = R6 * dx + R7 * dy + R8 * dz;
        Px[k] = cx; Py[k] = cy; Pz[k] = cz;
        float zz = cz * pr2;
        Qx[k] = (cx * pr0) / zz;
        Qy[k] = (cy * pr1) / zz;
        const float* cc = cols + ((size_t)b * PP + vi[k]) * 3;
        C[k][0] = cc[0]; C[k][1] = cc[1]; C[k][2] = cc[2];
    }

    // normal = cross(p1 - p0, p2 - p0)
    float ux = Px[1] - Px[0], uy = Py[1] - Py[0], uz = Pz[1] - Pz[0];
    float vx = Px[2] - Px[0], vy = Py[2] - Py[0], vz = Pz[2] - Pz[0];
    float nx = uy * vz - uz * vy;
    float ny = uz * vx - ux * vz;
    float nz = ux * vy - uy * vx;
    float inv = 1.0f / sqrtf(nx * nx + ny * ny + nz * nz + 1e-10f);

    // normal1 output: after imrender (B*H*W*3) and improb (B*H*W)
    size_t noff = (size_t)BB * HH * WW * 3 + (size_t)BB * HH * WW + ((size_t)b * FF + f) * 3;
    out[noff + 0] = nx * inv;
    out[noff + 1] = ny * inv;
    out[noff + 2] = nz * inv;

    FaceData fd;
    fd.x0 = Qx[0]; fd.y0 = Qy[0];
    fd.x1 = Qx[1]; fd.y1 = Qy[1];
    fd.x2 = Qx[2]; fd.y2 = Qy[2];

    float denom = (Qy[1] - Qy[2]) * (Qx[0] - Qx[2]) + (Qx[2] - Qx[1]) * (Qy[0] - Qy[2]);
    if (fabsf(denom) < 1e-10f) denom = 1e-10f;
    fd.invden = 1.0f / denom;
    fd.a0 = Qy[1] - Qy[2]; fd.b0 = Qx[2] - Qx[1];
    fd.a1 = Qy[2] - Qy[0]; fd.b1 = Qx[0] - Qx[2];
    fd.z0 = Pz[0]; fd.z1 = Pz[1]; fd.z2 = Pz[2];

    float ex, ey;
    ex = Qx[1] - Qx[0]; ey = Qy[1] - Qy[0];
    fd.e01x = ex; fd.e01y = ey; fd.i01 = 1.0f / (ex * ex + ey * ey + 1e-10f);
    ex = Qx[2] - Qx[1]; ey = Qy[2] - Qy[1];
    fd.e12x = ex; fd.e12y = ey; fd.i12 = 1.0f / (ex * ex + ey * ey + 1e-10f);
    ex = Qx[0] - Qx[2]; ey = Qy[0] - Qy[2];
    fd.e20x = ex; fd.e20y = ey; fd.i20 = 1.0f / (ex * ex + ey * ey + 1e-10f);

    fd.c00 = C[0][0]; fd.c01 = C[0][1]; fd.c02 = C[0][2];
    fd.c10 = C[1][0]; fd.c11 = C[1][1]; fd.c12 = C[1][2];
    fd.c20 = C[2][0]; fd.c21 = C[2][1]; fd.c22 = C[2][2];
    fd.front = (nz > 0.0f) ? 1.0f : 0.0f;

    g_face[b][f] = fd;
}

// ---------------------------------------------------------------------------
// Kernel 2: per-pixel render. One thread = one pixel; 256 faces from shared.
// ---------------------------------------------------------------------------
__global__ void __launch_bounds__(256) vcr_render_kernel(float* __restrict__ out)
{
    int b = blockIdx.y;
    __shared__ FaceData sf[FF];
    {
        const float* src = (const float*)(&g_face[b][0]);
        float* dst = (float*)sf;
        const int nwords = FF * (int)(sizeof(FaceData) / 4);
        for (int i = threadIdx.x; i < nwords; i += blockDim.x) dst[i] = src[i];
    }
    __syncthreads();

    int pix = blockIdx.x * blockDim.x + threadIdx.x;
    if (pix >= HH * WW) return;
    int y = pix / WW;
    int x = pix - y * WW;
    float px = (2.0f * x + 1.0f) * (1.0f / WW) - 1.0f;
    float py = 1.0f - (2.0f * y + 1.0f) * (1.0f / HH);

    float best = -1e10f;
    int   bi   = 0;
    float bl0 = 0.0f, bl1 = 0.0f, bl2 = 0.0f;
    bool  any = false;
    float logsum = 0.0f;
    const float LOG_IN = log1pf(-(1.0f - 1e-7f));   // inside-face contribution (constant)
    const float D2CUT = 88.0f * SIGMA_F;             // expf underflow threshold (matches fp32 ref)

    for (int f = 0; f < FF; f++) {
        const FaceData& fc = sf[f];
        if (fc.front == 0.0f) continue;  // warp-uniform: back faces contribute nothing

        float dx2 = px - fc.x2, dy2 = py - fc.y2;
        float l0 = (fc.a0 * dx2 + fc.b0 * dy2) * fc.invden;
        float l1 = (fc.a1 * dx2 + fc.b1 * dy2) * fc.invden;
        float l2 = 1.0f - l0 - l1;

        if (l0 >= 0.0f && l1 >= 0.0f && l2 >= 0.0f) {
            float z = l0 * fc.z0 + l1 * fc.z1 + l2 * fc.z2;
            if (z > best) { best = z; bi = f; bl0 = l0; bl1 = l1; bl2 = l2; }
            any = true;
            logsum += LOG_IN;
        } else {
            // min squared distance to the 3 edges
            float pax = px - fc.x0, pay = py - fc.y0;
            float t = fminf(fmaxf((pax * fc.e01x + pay * fc.e01y) * fc.i01, 0.0f), 1.0f);
            float ddx = pax - t * fc.e01x, ddy = pay - t * fc.e01y;
            float d2 = ddx * ddx + ddy * ddy;

            pax = px - fc.x1; pay = py - fc.y1;
            t = fminf(fmaxf((pax * fc.e12x + pay * fc.e12y) * fc.i12, 0.0f), 1.0f);
            ddx = pax - t * fc.e12x; ddy = pay - t * fc.e12y;
            float d2b = ddx * ddx + ddy * ddy;
            d2 = fminf(d2, d2b);

            pax = px - fc.x2; pay = py - fc.y2;
            t = fminf(fmaxf((pax * fc.e20x + pay * fc.e20y) * fc.i20, 0.0f), 1.0f);
            ddx = pax - t * fc.e20x; ddy = pay - t * fc.e20y;
            d2b = ddx * ddx + ddy * ddy;
            d2 = fminf(d2, d2b);

            if (d2 < D2CUT) {
                float p = expf(-d2 * (1.0f / SIGMA_F)) * (1.0f - 1e-7f);
                logsum += log1pf(-p);
            }
        }
    }

    const FaceData& fb = sf[bi];
    float m = any ? 1.0f : 0.0f;
    float r  = (bl0 * fb.c00 + bl1 * fb.c10 + bl2 * fb.c20) * m;
    float g  = (bl0 * fb.c01 + bl1 * fb.c11 + bl2 * fb.c21) * m;
    float bl = (bl0 * fb.c02 + bl1 * fb.c12 + bl2 * fb.c22) * m;

    size_t ro = ((size_t)(b * HH + y) * WW + x) * 3;
    out[ro + 0] = r;
    out[ro + 1] = g;
    out[ro + 2] = bl;

    size_t po = (size_t)BB * HH * WW * 3 + (size_t)(b * HH + y) * WW + x;
    out[po] = 1.0f - expf(logsum);
}

extern "C" void kernel_launch(void* const* d_in, const int* in_sizes, int n_in,
                              void* d_out, int out_size)
{
    const float* pts   = (const float*)d_in[0];   // points_bxpx3 (2,2048,3)
    const int*   faces = (const int*)d_in[1];     // faces_fx3 (256,3)
    const float* rot   = (const float*)d_in[2];   // camera_rot (2,3,3)
    const float* pos   = (const float*)d_in[3];   // camera_pos (2,3)
    const float* proj  = (const float*)d_in[4];   // camera_proj (3,1)
    const float* cols  = (const float*)d_in[5];   // colors_bxpx3 (2,2048,3)
    float* out = (float*)d_out;

    vcr_prep_kernel<<<BB, FF>>>(pts, faces, rot, pos, proj, cols, out);

    dim3 grid((HH * WW + 255) / 256, BB);
    vcr_render_kernel<<<grid, 256>>>(out);
}

// round 2
// speedup vs baseline: 1.6963x; 1.6963x over previous
#include <cuda_runtime.h>
#include <math.h>

#define HH 224
#define WW 224
#define BB 2
#define PP 2048
#define FF 256
#define SIGMA_F 0.0003f
#define INV_SIGMA 3333.3333333f
#define D2CUT (88.0f * SIGMA_F)     // exp underflow threshold: matches fp32 reference behavior
#define NV4 10                       // float4s per face

// Face data layout (float4 x 10 per face):
// v0: x2, y2, A0, B0          (A0=a0*invden, B0=b0*invden)
// v1: A1, B1, z0, z1
// v2: z2, k0, k1, k2          (k_i = denom^2 / (|e_opp|^2+eps)  -> lower-bound dist^2 scale)
// v3: x0, y0, x1, y1
// v4: e01x, e01y, i01, 0
// v5: e12x, e12y, i12, 0
// v6: e20x, e20y, i20, 0
// v7: c00, c01, c02, c10
// v8: c11, c12, c20, c21
// v9: c22, 0, 0, 0

__device__ float4 g_face4[BB][FF][NV4];
__device__ int    g_cnt[BB];

// ---------------------------------------------------------------------------
// Prep: one block per batch (256 threads = 256 faces). Computes per-face data,
// writes normal1 output, and compacts front faces (order-preserving scan).
// ---------------------------------------------------------------------------
__global__ void vcr_prep_kernel(const float* __restrict__ pts,
                                const int*   __restrict__ faces,
                                const float* __restrict__ rot,
                                const float* __restrict__ pos,
                                const float* __restrict__ proj,
                                const float* __restrict__ cols,
                                float* __restrict__ out)
{
    int b = blockIdx.x;
    int f = threadIdx.x;

    float R0 = rot[b*9+0], R1 = rot[b*9+1], R2 = rot[b*9+2];
    float R3 = rot[b*9+3], R4 = rot[b*9+4], R5 = rot[b*9+5];
    float R6 = rot[b*9+6], R7 = rot[b*9+7], R8 = rot[b*9+8];
    float cpx = pos[b*3+0], cpy = pos[b*3+1], cpz = pos[b*3+2];
    float pr0 = proj[0], pr1 = proj[1], pr2 = proj[2];

    int vi[3] = { faces[f*3+0], faces[f*3+1], faces[f*3+2] };

    float Px[3], Py[3], Pz[3], Qx[3], Qy[3], C[3][3];
    #pragma unroll
    for (int k = 0; k < 3; k++) {
        const float* pp = pts + ((size_t)b * PP + vi[k]) * 3;
        float dx = pp[0]-cpx, dy = pp[1]-cpy, dz = pp[2]-cpz;
        float cx = R0*dx + R1*dy + R2*dz;
        float cy = R3*dx + R4*dy + R5*dz;
        float cz = R6*dx + R7*dy + R8*dz;
        Px[k]=cx; Py[k]=cy; Pz[k]=cz;
        float zz = cz * pr2;
        Qx[k] = (cx*pr0)/zz;
        Qy[k] = (cy*pr1)/zz;
        const float* cc = cols + ((size_t)b * PP + vi[k]) * 3;
        C[k][0]=cc[0]; C[k][1]=cc[1]; C[k][2]=cc[2];
    }

    float ux=Px[1]-Px[0], uy=Py[1]-Py[0], uz=Pz[1]-Pz[0];
    float vx=Px[2]-Px[0], vy=Py[2]-Py[0], vz=Pz[2]-Pz[0];
    float nx = uy*vz - uz*vy;
    float ny = uz*vx - ux*vz;
    float nz = ux*vy - uy*vx;
    float inv = 1.0f / sqrtf(nx*nx + ny*ny + nz*nz + 1e-10f);

    size_t noff = (size_t)BB*HH*WW*3 + (size_t)BB*HH*WW + ((size_t)b*FF + f)*3;
    out[noff+0] = nx*inv;
    out[noff+1] = ny*inv;
    out[noff+2] = nz*inv;

    bool front = (nz > 0.0f);

    // order-preserving compaction
    __shared__ int warp_off[9];
    unsigned mask = __ballot_sync(0xffffffffu, front);
    int lane = threadIdx.x & 31, wid = threadIdx.x >> 5;
    if (lane == 0) warp_off[wid] = __popc(mask);
    __syncthreads();
    if (threadIdx.x == 0) {
        int s = 0;
        for (int i = 0; i < 8; i++) { int t = warp_off[i]; warp_off[i] = s; s += t; }
        g_cnt[b] = s;
    }
    __syncthreads();
    if (!front) return;
    int slot = warp_off[wid] + __popc(mask & ((1u << lane) - 1u));

    float denom = (Qy[1]-Qy[2])*(Qx[0]-Qx[2]) + (Qx[2]-Qx[1])*(Qy[0]-Qy[2]);
    if (fabsf(denom) < 1e-10f) denom = 1e-10f;
    float invden = 1.0f / denom;
    float den2 = denom * denom;

    float e01x = Qx[1]-Qx[0], e01y = Qy[1]-Qy[0];
    float e12x = Qx[2]-Qx[1], e12y = Qy[2]-Qy[1];
    float e20x = Qx[0]-Qx[2], e20y = Qy[0]-Qy[2];
    float i01 = 1.0f/(e01x*e01x + e01y*e01y + 1e-10f);
    float i12 = 1.0f/(e12x*e12x + e12y*e12y + 1e-10f);
    float i20 = 1.0f/(e20x*e20x + e20y*e20y + 1e-10f);

    float4* dst = &g_face4[b][slot][0];
    dst[0] = make_float4(Qx[2], Qy[2], (Qy[1]-Qy[2])*invden, (Qx[2]-Qx[1])*invden);
    dst[1] = make_float4((Qy[2]-Qy[0])*invden, (Qx[0]-Qx[2])*invden, Pz[0], Pz[1]);
    dst[2] = make_float4(Pz[2], den2*i12, den2*i20, den2*i01);
    dst[3] = make_float4(Qx[0], Qy[0], Qx[1], Qy[1]);
    dst[4] = make_float4(e01x, e01y, i01, 0.0f);
    dst[5] = make_float4(e12x, e12y, i12, 0.0f);
    dst[6] = make_float4(e20x, e20y, i20, 0.0f);
    dst[7] = make_float4(C[0][0], C[0][1], C[0][2], C[1][0]);
    dst[8] = make_float4(C[1][1], C[1][2], C[2][0], C[2][1]);
    dst[9] = make_float4(C[2][2], 0.0f, 0.0f, 0.0f);
}

// ---------------------------------------------------------------------------
// Render: 128 threads/block, 2 adjacent pixels per thread (256 px per block).
// ---------------------------------------------------------------------------
__global__ void __launch_bounds__(128) vcr_render_kernel(float* __restrict__ out)
{
    int b = blockIdx.y;
    __shared__ float4 sf[FF * NV4];
    __shared__ int scnt;
    {
        const float4* src = &g_face4[b][0][0];
        for (int i = threadIdx.x; i < FF * NV4; i += blockDim.x) sf[i] = src[i];
        if (threadIdx.x == 0) scnt = g_cnt[b];
    }
    __syncthreads();
    int cnt = scnt;

    int pix = blockIdx.x * 256 + threadIdx.x * 2;
    int y = pix / WW;
    int xb = pix - y * WW;           // even, xb+1 in same row (WW even)
    float py = 1.0f - (2.0f*y + 1.0f) * (1.0f/HH);
    float pxv[2];
    pxv[0] = (2.0f*xb + 1.0f) * (1.0f/WW) - 1.0f;
    pxv[1] = pxv[0] + 2.0f*(1.0f/WW);

    const float IN_F = 1.0f - (1.0f - 1e-7f);   // exact (Sterbenz)

    float best[2] = {-1e10f, -1e10f};
    int   bi[2]   = {-1, -1};
    float bl0[2], bl1[2], bl2[2];
    float prod[2] = {1.0f, 1.0f};

    for (int f = 0; f < cnt; f++) {
        const float4* fp = &sf[f * NV4];
        float4 v0 = fp[0];
        float4 v1 = fp[1];
        float4 v2 = fp[2];

        #pragma unroll
        for (int j = 0; j < 2; j++) {
            float px = pxv[j];
            float dx = px - v0.x, dy = py - v0.y;
            float l0 = v0.z*dx + v0.w*dy;
            float l1 = v1.x*dx + v1.y*dy;
            float l2 = 1.0f - l0 - l1;

            if (l0 >= 0.0f && l1 >= 0.0f && l2 >= 0.0f) {
                float z = l0*v1.z + l1*v1.w + l2*v2.x;
                if (z > best[j]) { best[j] = z; bi[j] = f; bl0[j] = l0; bl1[j] = l1; bl2[j] = l2; }
                prod[j] *= IN_F;
            } else {
                // conservative lower bound on squared distance to boundary
                float lb2 = 0.0f;
                if (l0 < 0.0f) lb2 = l0*l0*v2.y;
                if (l1 < 0.0f) lb2 = fmaxf(lb2, l1*l1*v2.z);
                if (l2 < 0.0f) lb2 = fmaxf(lb2, l2*l2*v2.w);
                if (lb2 < D2CUT) {
                    float4 v3 = fp[3];
                    float4 v4 = fp[4];
                    float4 v5 = fp[5];
                    float4 v6 = fp[6];

                    float pax = px - v3.x, pay = py - v3.y;     // vs v0
                    float t = fminf(fmaxf((pax*v4.x + pay*v4.y)*v4.z, 0.0f), 1.0f);
                    float ddx = pax - t*v4.x, ddy = pay - t*v4.y;
                    float d2 = ddx*ddx + ddy*ddy;

                    pax = px - v3.z; pay = py - v3.w;           // vs v1
                    t = fminf(fmaxf((pax*v5.x + pay*v5.y)*v5.z, 0.0f), 1.0f);
                    ddx = pax - t*v5.x; ddy = pay - t*v5.y;
                    d2 = fminf(d2, ddx*ddx + ddy*ddy);

                    pax = px - v0.x; pay = py - v0.y;           // vs v2
                    t = fminf(fmaxf((pax*v6.x + pay*v6.y)*v6.z, 0.0f), 1.0f);
                    ddx = pax - t*v6.x; ddy = pay - t*v6.y;
                    d2 = fminf(d2, ddx*ddx + ddy*ddy);

                    if (d2 < D2CUT) {
                        float p = __expf(-d2 * INV_SIGMA) * (1.0f - 1e-7f);
                        prod[j] *= fmaxf(1.0f - p, 0.0f);
                    }
                }
            }
        }
    }

    #pragma unroll
    for (int j = 0; j < 2; j++) {
        float r = 0.0f, g = 0.0f, bcol = 0.0f;
        if (bi[j] >= 0) {
            const float4* fp = &sf[bi[j] * NV4];
            float4 c0 = fp[7];
            float4 c1 = fp[8];
            float4 c2 = fp[9];
            r    = bl0[j]*c0.x + bl1[j]*c0.w + bl2[j]*c1.z;
            g    = bl0[j]*c0.y + bl1[j]*c1.x + bl2[j]*c1.w;
            bcol = bl0[j]*c0.z + bl1[j]*c1.y + bl2[j]*c2.x;
        }
        int x = xb + j;
        size_t ro = ((size_t)(b*HH + y)*WW + x)*3;
        out[ro+0] = r;
        out[ro+1] = g;
        out[ro+2] = bcol;
        size_t po = (size_t)BB*HH*WW*3 + (size_t)(b*HH + y)*WW + x;
        out[po] = 1.0f - prod[j];
    }
}

extern "C" void kernel_launch(void* const* d_in, const int* in_sizes, int n_in,
                              void* d_out, int out_size)
{
    const float* pts   = (const float*)d_in[0];
    const int*   faces = (const int*)d_in[1];
    const float* rot   = (const float*)d_in[2];
    const float* pos   = (const float*)d_in[3];
    const float* proj  = (const float*)d_in[4];
    const float* cols  = (const float*)d_in[5];
    float* out = (float*)d_out;

    vcr_prep_kernel<<<BB, FF>>>(pts, faces, rot, pos, proj, cols, out);

    dim3 grid((HH*WW)/256, BB);   // 196 x 2 = 392 blocks
    vcr_render_kernel<<<grid, 128>>>(out);
}

// round 3
// speedup vs baseline: 2.5835x; 1.5230x over previous
#include <cuda_runtime.h>
#include <math.h>

#define HH 224
#define WW 224
#define BB 2
#define PP 2048
#define FF 256
#define SIGMA_F 0.0003f
#define INV_SIGMA 3333.3333333f
#define D2CUT (88.0f * SIGMA_F)     // exp underflow threshold: matches fp32 reference behavior
#define NV4 10                       // float4s per face in global staging

// Face data layout in g_face4 (float4 x 10 per face):
// [0]: x2, y2, A0, B0          (A0=a0*invden, B0=b0*invden)
// [1]: A1, B1, z0, z1
// [2]: z2, k12, k20, k01       (k = denom^2/(|e|^2+eps): lower-bound dist^2 scale)
// [3]: x0, y0, x1, y1
// [4]: e01x, e01y, i01, 0
// [5]: e12x, e12y, i12, 0
// [6]: e20x, e20y, i20, 0
// [7]: c00, c01, c02, c10
// [8]: c11, c12, c20, c21
// [9]: c22, 0, 0, 0

__device__ float4 g_face4[BB][FF][NV4];
__device__ int    g_cnt[BB];

// ---------------------------------------------------------------------------
// Prep: one block per batch (256 threads = 256 faces).
// ---------------------------------------------------------------------------
__global__ void vcr_prep_kernel(const float* __restrict__ pts,
                                const int*   __restrict__ faces,
                                const float* __restrict__ rot,
                                const float* __restrict__ pos,
                                const float* __restrict__ proj,
                                const float* __restrict__ cols,
                                float* __restrict__ out)
{
    int b = blockIdx.x;
    int f = threadIdx.x;

    float R0 = rot[b*9+0], R1 = rot[b*9+1], R2 = rot[b*9+2];
    float R3 = rot[b*9+3], R4 = rot[b*9+4], R5 = rot[b*9+5];
    float R6 = rot[b*9+6], R7 = rot[b*9+7], R8 = rot[b*9+8];
    float cpx = pos[b*3+0], cpy = pos[b*3+1], cpz = pos[b*3+2];
    float pr0 = proj[0], pr1 = proj[1], pr2 = proj[2];

    int vi[3] = { faces[f*3+0], faces[f*3+1], faces[f*3+2] };

    float Px[3], Py[3], Pz[3], Qx[3], Qy[3], C[3][3];
    #pragma unroll
    for (int k = 0; k < 3; k++) {
        const float* pp = pts + ((size_t)b * PP + vi[k]) * 3;
        float dx = pp[0]-cpx, dy = pp[1]-cpy, dz = pp[2]-cpz;
        float cx = R0*dx + R1*dy + R2*dz;
        float cy = R3*dx + R4*dy + R5*dz;
        float cz = R6*dx + R7*dy + R8*dz;
        Px[k]=cx; Py[k]=cy; Pz[k]=cz;
        float zz = cz * pr2;
        Qx[k] = (cx*pr0)/zz;
        Qy[k] = (cy*pr1)/zz;
        const float* cc = cols + ((size_t)b * PP + vi[k]) * 3;
        C[k][0]=cc[0]; C[k][1]=cc[1]; C[k][2]=cc[2];
    }

    float ux=Px[1]-Px[0], uy=Py[1]-Py[0], uz=Pz[1]-Pz[0];
    float vx=Px[2]-Px[0], vy=Py[2]-Py[0], vz=Pz[2]-Pz[0];
    float nx = uy*vz - uz*vy;
    float ny = uz*vx - ux*vz;
    float nz = ux*vy - uy*vx;
    float inv = 1.0f / sqrtf(nx*nx + ny*ny + nz*nz + 1e-10f);

    size_t noff = (size_t)BB*HH*WW*3 + (size_t)BB*HH*WW + ((size_t)b*FF + f)*3;
    out[noff+0] = nx*inv;
    out[noff+1] = ny*inv;
    out[noff+2] = nz*inv;

    bool front = (nz > 0.0f);

    // order-preserving compaction (argmax tie order must match reference)
    __shared__ int warp_off[9];
    unsigned mask = __ballot_sync(0xffffffffu, front);
    int lane = threadIdx.x & 31, wid = threadIdx.x >> 5;
    if (lane == 0) warp_off[wid] = __popc(mask);
    __syncthreads();
    if (threadIdx.x == 0) {
        int s = 0;
        for (int i = 0; i < 8; i++) { int t = warp_off[i]; warp_off[i] = s; s += t; }
        g_cnt[b] = s;
    }
    __syncthreads();
    if (!front) return;
    int slot = warp_off[wid] + __popc(mask & ((1u << lane) - 1u));

    float denom = (Qy[1]-Qy[2])*(Qx[0]-Qx[2]) + (Qx[2]-Qx[1])*(Qy[0]-Qy[2]);
    if (fabsf(denom) < 1e-10f) denom = 1e-10f;
    float invden = 1.0f / denom;
    float den2 = denom * denom;

    float e01x = Qx[1]-Qx[0], e01y = Qy[1]-Qy[0];
    float e12x = Qx[2]-Qx[1], e12y = Qy[2]-Qy[1];
    float e20x = Qx[0]-Qx[2], e20y = Qy[0]-Qy[2];
    float i01 = 1.0f/(e01x*e01x + e01y*e01y + 1e-10f);
    float i12 = 1.0f/(e12x*e12x + e12y*e12y + 1e-10f);
    float i20 = 1.0f/(e20x*e20x + e20y*e20y + 1e-10f);

    float4* dst = &g_face4[b][slot][0];
    dst[0] = make_float4(Qx[2], Qy[2], (Qy[1]-Qy[2])*invden, (Qx[2]-Qx[1])*invden);
    dst[1] = make_float4((Qy[2]-Qy[0])*invden, (Qx[0]-Qx[2])*invden, Pz[0], Pz[1]);
    dst[2] = make_float4(Pz[2], den2*i12, den2*i20, den2*i01);
    dst[3] = make_float4(Qx[0], Qy[0], Qx[1], Qy[1]);
    dst[4] = make_float4(e01x, e01y, i01, 0.0f);
    dst[5] = make_float4(e12x, e12y, i12, 0.0f);
    dst[6] = make_float4(e20x, e20y, i20, 0.0f);
    dst[7] = make_float4(C[0][0], C[0][1], C[0][2], C[1][0]);
    dst[8] = make_float4(C[1][1], C[1][2], C[2][0], C[2][1]);
    dst[9] = make_float4(C[2][2], 0.0f, 0.0f, 0.0f);
}

// ---------------------------------------------------------------------------
// Render: 128 threads/block, 1 pixel/thread, 16x8 tile per block.
// Shared: hot barycentric data (12 KB) + edge data (16 KB). Colors from global.
// ---------------------------------------------------------------------------
__global__ void __launch_bounds__(128) vcr_render_kernel(float* __restrict__ out)
{
    int b = blockIdx.z;
    __shared__ float4 sf_hot[FF * 3];
    __shared__ float4 sf_edge[FF * 4];
    __shared__ int scnt;
    {
        const float4* src = &g_face4[b][0][0];
        for (int i = threadIdx.x; i < FF * 3; i += 128) {
            int f = i / 3, k = i - f * 3;
            sf_hot[i] = src[f * NV4 + k];
        }
        for (int i = threadIdx.x; i < FF * 4; i += 128) {
            int f = i >> 2, k = i & 3;
            sf_edge[i] = src[f * NV4 + 3 + k];
        }
        if (threadIdx.x == 0) scnt = g_cnt[b];
    }
    __syncthreads();
    int cnt = scnt;

    int x = blockIdx.x * 16 + (threadIdx.x & 15);
    int y = blockIdx.y * 8  + (threadIdx.x >> 4);
    float px = (2.0f*x + 1.0f) * (1.0f/WW) - 1.0f;
    float py = 1.0f - (2.0f*y + 1.0f) * (1.0f/HH);

    const float IN_F = 1.0f - (1.0f - 1e-7f);   // exact (Sterbenz)

    float best = -1e10f;
    int   bi   = -1;
    float bl0 = 0.0f, bl1 = 0.0f, bl2 = 0.0f;
    float prod = 1.0f;

    for (int f = 0; f < cnt; f++) {
        float4 v0 = sf_hot[f*3+0];
        float4 v1 = sf_hot[f*3+1];
        float4 v2 = sf_hot[f*3+2];

        float dx = px - v0.x, dy = py - v0.y;
        float l0 = fmaf(v0.z, dx, v0.w * dy);
        float l1 = fmaf(v1.x, dx, v1.y * dy);
        float l2 = 1.0f - l0 - l1;

        if (fminf(l0, fminf(l1, l2)) >= 0.0f) {
            float z = l0*v1.z + l1*v1.w + l2*v2.x;
            if (z > best) { best = z; bi = f; bl0 = l0; bl1 = l1; bl2 = l2; }
            prod *= IN_F;
        } else {
            // conservative lower bound on squared distance to the boundary
            float lb2 = 0.0f;
            if (l0 < 0.0f) lb2 = l0*l0*v2.y;
            if (l1 < 0.0f) lb2 = fmaxf(lb2, l1*l1*v2.z);
            if (l2 < 0.0f) lb2 = fmaxf(lb2, l2*l2*v2.w);
            if (lb2 < D2CUT) {
                float4 v3 = sf_edge[f*4+0];
                float4 v4 = sf_edge[f*4+1];
                float4 v5 = sf_edge[f*4+2];
                float4 v6 = sf_edge[f*4+3];

                float pax = px - v3.x, pay = py - v3.y;     // from v0
                float t = fminf(fmaxf((pax*v4.x + pay*v4.y)*v4.z, 0.0f), 1.0f);
                float ddx = pax - t*v4.x, ddy = pay - t*v4.y;
                float d2 = ddx*ddx + ddy*ddy;

                pax = px - v3.z; pay = py - v3.w;           // from v1
                t = fminf(fmaxf((pax*v5.x + pay*v5.y)*v5.z, 0.0f), 1.0f);
                ddx = pax - t*v5.x; ddy = pay - t*v5.y;
                d2 = fminf(d2, ddx*ddx + ddy*ddy);

                pax = px - v0.x; pay = py - v0.y;           // from v2
                t = fminf(fmaxf((pax*v6.x + pay*v6.y)*v6.z, 0.0f), 1.0f);
                ddx = pax - t*v6.x; ddy = pay - t*v6.y;
                d2 = fminf(d2, ddx*ddx + ddy*ddy);

                if (d2 < D2CUT) {
                    float p = __expf(-d2 * INV_SIGMA) * (1.0f - 1e-7f);
                    prod *= fmaxf(1.0f - p, 0.0f);
                }
            }
        }
    }

    float r = 0.0f, g = 0.0f, bcol = 0.0f;
    if (bi >= 0) {
        const float4* fp = &g_face4[b][bi][7];
        float4 c0 = fp[0];
        float4 c1 = fp[1];
        float4 c2 = fp[2];
        r    = bl0*c0.x + bl1*c0.w + bl2*c1.z;
        g    = bl0*c0.y + bl1*c1.x + bl2*c1.w;
        bcol = bl0*c0.z + bl1*c1.y + bl2*c2.x;
    }

    size_t ro = ((size_t)(b*HH + y)*WW + x)*3;
    out[ro+0] = r;
    out[ro+1] = g;
    out[ro+2] = bcol;
    size_t po = (size_t)BB*HH*WW*3 + (size_t)(b*HH + y)*WW + x;
    out[po] = 1.0f - prod;
}

extern "C" void kernel_launch(void* const* d_in, const int* in_sizes, int n_in,
                              void* d_out, int out_size)
{
    const float* pts   = (const float*)d_in[0];
    const int*   faces = (const int*)d_in[1];
    const float* rot   = (const float*)d_in[2];
    const float* pos   = (const float*)d_in[3];
    const float* proj  = (const float*)d_in[4];
    const float* cols  = (const float*)d_in[5];
    float* out = (float*)d_out;

    vcr_prep_kernel<<<BB, FF>>>(pts, faces, rot, pos, proj, cols, out);

    dim3 grid(WW/16, HH/8, BB);   // 14 x 28 x 2 = 784 blocks
    vcr_render_kernel<<<grid, 128>>>(out);
}

// round 4
// speedup vs baseline: 2.9021x; 1.1233x over previous
#include <cuda_runtime.h>
#include <math.h>

#define HH 224
#define WW 224
#define BB 2
#define PP 2048
#define FF 256
#define SIGMA_F 0.0003f
#define INV_SIGMA 3333.3333333f
#define D2CUT (88.0f * SIGMA_F)      // exp underflow threshold (matches fp32 reference)
#define MARGIN 0.16248077f           // sqrt(D2CUT)
#define NV4 10                       // float4s per face in global staging

// Face data layout in g_face4 (float4 x 10 per face):
// [0]: x2, y2, A0, B0
// [1]: A1, B1, z0, z1
// [2]: z2, k12, k20, k01
// [3]: x0, y0, x1, y1
// [4]: e01x, e01y, i01, 0
// [5]: e12x, e12y, i12, 0
// [6]: e20x, e20y, i20, 0
// [7..9]: colors
__device__ float4 g_face4[BB][FF][NV4];
__device__ float4 g_bbox[BB][FF];    // xmin, ymin, xmax, ymax (compacted slots)
__device__ int    g_cnt[BB];

// ---------------------------------------------------------------------------
// Prep: one block per batch (256 threads = 256 faces).
// ---------------------------------------------------------------------------
__global__ void vcr_prep_kernel(const float* __restrict__ pts,
                                const int*   __restrict__ faces,
                                const float* __restrict__ rot,
                                const float* __restrict__ pos,
                                const float* __restrict__ proj,
                                const float* __restrict__ cols,
                                float* __restrict__ out)
{
    int b = blockIdx.x;
    int f = threadIdx.x;

    float R0 = rot[b*9+0], R1 = rot[b*9+1], R2 = rot[b*9+2];
    float R3 = rot[b*9+3], R4 = rot[b*9+4], R5 = rot[b*9+5];
    float R6 = rot[b*9+6], R7 = rot[b*9+7], R8 = rot[b*9+8];
    float cpx = pos[b*3+0], cpy = pos[b*3+1], cpz = pos[b*3+2];
    float pr0 = proj[0], pr1 = proj[1], pr2 = proj[2];

    int vi[3] = { faces[f*3+0], faces[f*3+1], faces[f*3+2] };

    float Px[3], Py[3], Pz[3], Qx[3], Qy[3], C[3][3];
    #pragma unroll
    for (int k = 0; k < 3; k++) {
        const float* pp = pts + ((size_t)b * PP + vi[k]) * 3;
        float dx = pp[0]-cpx, dy = pp[1]-cpy, dz = pp[2]-cpz;
        float cx = R0*dx + R1*dy + R2*dz;
        float cy = R3*dx + R4*dy + R5*dz;
        float cz = R6*dx + R7*dy + R8*dz;
        Px[k]=cx; Py[k]=cy; Pz[k]=cz;
        float zz = cz * pr2;
        Qx[k] = (cx*pr0)/zz;
        Qy[k] = (cy*pr1)/zz;
        const float* cc = cols + ((size_t)b * PP + vi[k]) * 3;
        C[k][0]=cc[0]; C[k][1]=cc[1]; C[k][2]=cc[2];
    }

    float ux=Px[1]-Px[0], uy=Py[1]-Py[0], uz=Pz[1]-Pz[0];
    float vx=Px[2]-Px[0], vy=Py[2]-Py[0], vz=Pz[2]-Pz[0];
    float nx = uy*vz - uz*vy;
    float ny = uz*vx - ux*vz;
    float nz = ux*vy - uy*vx;
    float inv = 1.0f / sqrtf(nx*nx + ny*ny + nz*nz + 1e-10f);

    size_t noff = (size_t)BB*HH*WW*3 + (size_t)BB*HH*WW + ((size_t)b*FF + f)*3;
    out[noff+0] = nx*inv;
    out[noff+1] = ny*inv;
    out[noff+2] = nz*inv;

    bool front = (nz > 0.0f);

    // order-preserving compaction (argmax tie order must match reference)
    __shared__ int warp_off[9];
    unsigned mask = __ballot_sync(0xffffffffu, front);
    int lane = threadIdx.x & 31, wid = threadIdx.x >> 5;
    if (lane == 0) warp_off[wid] = __popc(mask);
    __syncthreads();
    if (threadIdx.x == 0) {
        int s = 0;
        for (int i = 0; i < 8; i++) { int t = warp_off[i]; warp_off[i] = s; s += t; }
        g_cnt[b] = s;
    }
    __syncthreads();
    if (!front) return;
    int slot = warp_off[wid] + __popc(mask & ((1u << lane) - 1u));

    float denom = (Qy[1]-Qy[2])*(Qx[0]-Qx[2]) + (Qx[2]-Qx[1])*(Qy[0]-Qy[2]);
    if (fabsf(denom) < 1e-10f) denom = 1e-10f;
    float invden = 1.0f / denom;
    float den2 = denom * denom;

    float e01x = Qx[1]-Qx[0], e01y = Qy[1]-Qy[0];
    float e12x = Qx[2]-Qx[1], e12y = Qy[2]-Qy[1];
    float e20x = Qx[0]-Qx[2], e20y = Qy[0]-Qy[2];
    float i01 = 1.0f/(e01x*e01x + e01y*e01y + 1e-10f);
    float i12 = 1.0f/(e12x*e12x + e12y*e12y + 1e-10f);
    float i20 = 1.0f/(e20x*e20x + e20y*e20y + 1e-10f);

    float4* dst = &g_face4[b][slot][0];
    dst[0] = make_float4(Qx[2], Qy[2], (Qy[1]-Qy[2])*invden, (Qx[2]-Qx[1])*invden);
    dst[1] = make_float4((Qy[2]-Qy[0])*invden, (Qx[0]-Qx[2])*invden, Pz[0], Pz[1]);
    dst[2] = make_float4(Pz[2], den2*i12, den2*i20, den2*i01);
    dst[3] = make_float4(Qx[0], Qy[0], Qx[1], Qy[1]);
    dst[4] = make_float4(e01x, e01y, i01, 0.0f);
    dst[5] = make_float4(e12x, e12y, i12, 0.0f);
    dst[6] = make_float4(e20x, e20y, i20, 0.0f);
    dst[7] = make_float4(C[0][0], C[0][1], C[0][2], C[1][0]);
    dst[8] = make_float4(C[1][1], C[1][2], C[2][0], C[2][1]);
    dst[9] = make_float4(C[2][2], 0.0f, 0.0f, 0.0f);

    float bxmin = fminf(Qx[0], fminf(Qx[1], Qx[2]));
    float bxmax = fmaxf(Qx[0], fmaxf(Qx[1], Qx[2]));
    float bymin = fminf(Qy[0], fminf(Qy[1], Qy[2]));
    float bymax = fmaxf(Qy[0], fmaxf(Qy[1], Qy[2]));
    g_bbox[b][slot] = make_float4(bxmin, bymin, bxmax, bymax);
}

// ---------------------------------------------------------------------------
// Render: 128 threads/block, 1 pixel/thread, 16x8 tile.
// Per-tile bbox cull -> compacted index list in shared.
// ---------------------------------------------------------------------------
__global__ void __launch_bounds__(128) vcr_render_kernel(float* __restrict__ out)
{
    int b = blockIdx.z;
    __shared__ float4 sf_hot[FF * 3];
    __shared__ float4 sf_edge[FF * 4];
    __shared__ int slist[FF];
    __shared__ int sbase;
    __shared__ int woff[4];
    __shared__ int scnt;
    {
        const float4* src = &g_face4[b][0][0];
        for (int i = threadIdx.x; i < FF * 3; i += 128) {
            int f = i / 3, k = i - f * 3;
            sf_hot[i] = src[f * NV4 + k];
        }
        for (int i = threadIdx.x; i < FF * 4; i += 128) {
            int f = i >> 2, k = i & 3;
            sf_edge[i] = src[f * NV4 + 3 + k];
        }
        if (threadIdx.x == 0) { scnt = g_cnt[b]; sbase = 0; }
    }
    __syncthreads();
    int cnt = scnt;

    // tile rect in NDC
    int tx0 = blockIdx.x * 16;
    int ty0 = blockIdx.y * 8;
    float txmin = (2.0f*tx0 + 1.0f) * (1.0f/WW) - 1.0f;
    float txmax = (2.0f*(tx0+15) + 1.0f) * (1.0f/WW) - 1.0f;
    float tymax = 1.0f - (2.0f*ty0 + 1.0f) * (1.0f/HH);
    float tymin = 1.0f - (2.0f*(ty0+7) + 1.0f) * (1.0f/HH);

    // order-preserving bbox cull (2 rounds of 128)
    int lane = threadIdx.x & 31, w = threadIdx.x >> 5;
    #pragma unroll
    for (int r = 0; r < 2; r++) {
        int f = r * 128 + threadIdx.x;
        bool keep = false;
        if (f < cnt) {
            float4 bb = g_bbox[b][f];
            keep = (bb.x - MARGIN <= txmax) & (bb.z + MARGIN >= txmin) &
                   (bb.y - MARGIN <= tymax) & (bb.w + MARGIN >= tymin);
        }
        unsigned mask = __ballot_sync(0xffffffffu, keep);
        if (lane == 0) woff[w] = __popc(mask);
        __syncthreads();
        if (threadIdx.x == 0) {
            int s = sbase;
            for (int i = 0; i < 4; i++) { int t = woff[i]; woff[i] = s; s += t; }
            sbase = s;
        }
        __syncthreads();
        if (keep) slist[woff[w] + __popc(mask & ((1u << lane) - 1u))] = f;
        __syncthreads();
    }
    int m = sbase;

    int x = tx0 + (threadIdx.x & 15);
    int y = ty0 + (threadIdx.x >> 4);
    float px = (2.0f*x + 1.0f) * (1.0f/WW) - 1.0f;
    float py = 1.0f - (2.0f*y + 1.0f) * (1.0f/HH);

    const float IN_F = 1.0f - (1.0f - 1e-7f);   // exact (Sterbenz)

    float best = -1e10f;
    int   bi   = -1;
    float bl0 = 0.0f, bl1 = 0.0f, bl2 = 0.0f;
    float prod = 1.0f;

    for (int i = 0; i < m; i++) {
        int f = slist[i];
        float4 v0 = sf_hot[f*3+0];
        float4 v1 = sf_hot[f*3+1];
        float4 v2 = sf_hot[f*3+2];

        float dx = px - v0.x, dy = py - v0.y;
        float l0 = fmaf(v0.z, dx, v0.w * dy);
        float l1 = fmaf(v1.x, dx, v1.y * dy);
        float l2 = 1.0f - l0 - l1;

        if (fminf(l0, fminf(l1, l2)) >= 0.0f) {
            float z = l0*v1.z + l1*v1.w + l2*v2.x;
            if (z > best) { best = z; bi = f; bl0 = l0; bl1 = l1; bl2 = l2; }
            prod *= IN_F;
        } else {
            float lb2 = 0.0f;
            if (l0 < 0.0f) lb2 = l0*l0*v2.y;
            if (l1 < 0.0f) lb2 = fmaxf(lb2, l1*l1*v2.z);
            if (l2 < 0.0f) lb2 = fmaxf(lb2, l2*l2*v2.w);
            if (lb2 < D2CUT) {
                float4 v3 = sf_edge[f*4+0];
                float4 v4 = sf_edge[f*4+1];
                float4 v5 = sf_edge[f*4+2];
                float4 v6 = sf_edge[f*4+3];

                float pax = px - v3.x, pay = py - v3.y;     // from v0
                float t = fminf(fmaxf((pax*v4.x + pay*v4.y)*v4.z, 0.0f), 1.0f);
                float ddx = pax - t*v4.x, ddy = pay - t*v4.y;
                float d2 = ddx*ddx + ddy*ddy;

                pax = px - v3.z; pay = py - v3.w;           // from v1
                t = fminf(fmaxf((pax*v5.x + pay*v5.y)*v5.z, 0.0f), 1.0f);
                ddx = pax - t*v5.x; ddy = pay - t*v5.y;
                d2 = fminf(d2, ddx*ddx + ddy*ddy);

                pax = px - v0.x; pay = py - v0.y;           // from v2
                t = fminf(fmaxf((pax*v6.x + pay*v6.y)*v6.z, 0.0f), 1.0f);
                ddx = pax - t*v6.x; ddy = pay - t*v6.y;
                d2 = fminf(d2, ddx*ddx + ddy*ddy);

                if (d2 < D2CUT) {
                    float p = __expf(-d2 * INV_SIGMA) * (1.0f - 1e-7f);
                    prod *= fmaxf(1.0f - p, 0.0f);
                }
            }
        }
    }

    float r = 0.0f, g = 0.0f, bcol = 0.0f;
    if (bi >= 0) {
        const float4* fp = &g_face4[b][bi][7];
        float4 c0 = fp[0];
        float4 c1 = fp[1];
        float4 c2 = fp[2];
        r    = bl0*c0.x + bl1*c0.w + bl2*c1.z;
        g    = bl0*c0.y + bl1*c1.x + bl2*c1.w;
        bcol = bl0*c0.z + bl1*c1.y + bl2*c2.x;
    }

    size_t ro = ((size_t)(b*HH + y)*WW + x)*3;
    out[ro+0] = r;
    out[ro+1] = g;
    out[ro+2] = bcol;
    size_t po = (size_t)BB*HH*WW*3 + (size_t)(b*HH + y)*WW + x;
    out[po] = 1.0f - prod;
}

extern "C" void kernel_launch(void* const* d_in, const int* in_sizes, int n_in,
                              void* d_out, int out_size)
{
    const float* pts   = (const float*)d_in[0];
    const int*   faces = (const int*)d_in[1];
    const float* rot   = (const float*)d_in[2];
    const float* pos   = (const float*)d_in[3];
    const float* proj  = (const float*)d_in[4];
    const float* cols  = (const float*)d_in[5];
    float* out = (float*)d_out;

    vcr_prep_kernel<<<BB, FF>>>(pts, faces, rot, pos, proj, cols, out);

    dim3 grid(WW/16, HH/8, BB);   // 14 x 28 x 2 = 784 blocks
    vcr_render_kernel<<<grid, 128>>>(out);
}